// round 5
// baseline (speedup 1.0000x reference)
#include <cuda_runtime.h>
#include <cstdint>
#include <cstddef>

#define T_STEPS 2048
#define NB      32
#define HDIM    256
#define G4H     1024
#define CLUSTER_SZ 8

// ---------------------------------------------------------------------------
// Scratch (device globals — no allocation allowed in kernel_launch)
// ---------------------------------------------------------------------------
__device__ float g_xw0[(size_t)NB * T_STEPS * G4H];    // 268 MB
__device__ float g_h0seq[(size_t)NB * T_STEPS * HDIM]; // 64 MB
__device__ float g_xw1[(size_t)NB * T_STEPS * G4H];    // 268 MB
__device__ float g_h1T[NB * HDIM];

// ---------------------------------------------------------------------------
// Packed fp32x2 helpers (Blackwell FFMA2 path — ptxas won't auto-fuse)
// ---------------------------------------------------------------------------
__device__ __forceinline__ uint64_t fma_x2(uint64_t a, uint64_t b, uint64_t c) {
    uint64_t d;
    asm("fma.rn.f32x2 %0, %1, %2, %3;" : "=l"(d) : "l"(a), "l"(b), "l"(c));
    return d;
}
__device__ __forceinline__ uint64_t pack2(float x, float y) {
    uint64_t d;
    asm("mov.b64 %0, {%1, %2};" : "=l"(d) : "f"(x), "f"(y));
    return d;
}
__device__ __forceinline__ void unpack2(uint64_t v, float& lo, float& hi) {
    asm("mov.b64 {%0, %1}, %2;" : "=f"(lo), "=f"(hi) : "l"(v));
}
__device__ __forceinline__ void lds_v2u64(uint64_t& a, uint64_t& b, uint32_t addr) {
    asm volatile("ld.shared.v2.u64 {%0, %1}, [%2];" : "=l"(a), "=l"(b) : "r"(addr));
}

#define MBARRIER_INIT(addr, count) \
    asm volatile("mbarrier.init.shared.b64 [%0], %1;" \
                 :: "r"((uint32_t)(addr)), "r"((uint32_t)(count)) : "memory")

#define MBARRIER_WAIT_PARITY(mbar_smem_addr, phase_parity) do { \
    uint32_t _mbar = (uint32_t)(mbar_smem_addr); \
    uint32_t _parity = (uint32_t)(phase_parity); \
    uint32_t _done; \
    asm volatile( \
        "{\n\t" \
        ".reg .pred p;\n\t" \
        "mbarrier.try_wait.parity.acquire.cta.shared::cta.b64 p, [%1], %2;\n\t" \
        "selp.b32 %0, 1, 0, p;\n\t" \
        "}" \
        : "=r"(_done) : "r"(_mbar), "r"(_parity) : "memory"); \
    if (!_done) { \
        asm volatile( \
            "{\n\t" \
            ".reg .pred P1;\n\t" \
            "WAIT_LOOP_%=:\n\t" \
            "mbarrier.try_wait.parity.acquire.cta.shared::cta.b64 P1, [%0], %1, 0x989680;\n\t" \
            "@P1 bra.uni WAIT_DONE_%=;\n\t" \
            "bra.uni WAIT_LOOP_%=;\n\t" \
            "WAIT_DONE_%=:\n\t" \
            "}" \
            :: "r"(_mbar), "r"(_parity) : "memory"); \
    } \
} while(0)

#define CLUSTER_SYNC() do { \
    asm volatile("barrier.cluster.arrive.aligned;" ::: "memory"); \
    asm volatile("barrier.cluster.wait.aligned;"   ::: "memory"); \
} while (0)

// ---------------------------------------------------------------------------
// GEMM: out[M x 1024] = A[M x K] @ W[K x 1024] + bias   (M = 65536)
// ---------------------------------------------------------------------------
template <int K>
__global__ __launch_bounds__(256)
void gemm_xw(const float* __restrict__ A, const float* __restrict__ W,
             const float* __restrict__ bias, float* __restrict__ out) {
    extern __shared__ float sm[];
    float* a_s = sm;               // [128][65] transposed A tile
    float* w_s = sm + 128 * 65;    // [128][64]

    const int tid = threadIdx.x;
    const long m0 = (long)blockIdx.x * 64;
    const int  n0 = blockIdx.y * 64;

    const int tn = (tid & 15) << 2;
    const int tm = (tid >> 4) << 2;

    const uint32_t ws_b = (uint32_t)__cvta_generic_to_shared(w_s);

    uint64_t acc01[4], acc23[4];
#pragma unroll
    for (int i = 0; i < 4; i++) { acc01[i] = 0ull; acc23[i] = 0ull; }

    for (int k0 = 0; k0 < K; k0 += 128) {
        for (int idx = tid; idx < 64 * 128; idx += 256) {
            int r = idx >> 7;
            int k = idx & 127;
            a_s[k * 65 + r] = A[(m0 + r) * K + k0 + k];
        }
        for (int idx = tid; idx < 128 * 16; idx += 256) {
            int k = idx >> 4, c4 = idx & 15;
            *reinterpret_cast<float4*>(w_s + k * 64 + c4 * 4) =
                *reinterpret_cast<const float4*>(W + (size_t)(k0 + k) * G4H + n0 + c4 * 4);
        }
        __syncthreads();

#pragma unroll 8
        for (int k = 0; k < 128; k++) {
            const float* ap = a_s + k * 65 + tm;
            float a0 = ap[0], a1 = ap[1], a2 = ap[2], a3 = ap[3];
            uint64_t b01, b23;
            lds_v2u64(b01, b23, ws_b + (uint32_t)(k * 64 + tn) * 4u);
            uint64_t aa;
            aa = pack2(a0, a0);
            acc01[0] = fma_x2(aa, b01, acc01[0]); acc23[0] = fma_x2(aa, b23, acc23[0]);
            aa = pack2(a1, a1);
            acc01[1] = fma_x2(aa, b01, acc01[1]); acc23[1] = fma_x2(aa, b23, acc23[1]);
            aa = pack2(a2, a2);
            acc01[2] = fma_x2(aa, b01, acc01[2]); acc23[2] = fma_x2(aa, b23, acc23[2]);
            aa = pack2(a3, a3);
            acc01[3] = fma_x2(aa, b01, acc01[3]); acc23[3] = fma_x2(aa, b23, acc23[3]);
        }
        __syncthreads();
    }

    float4 bv = *reinterpret_cast<const float4*>(bias + n0 + tn);
#pragma unroll
    for (int i = 0; i < 4; i++) {
        float4 o;
        unpack2(acc01[i], o.x, o.y);
        unpack2(acc23[i], o.z, o.w);
        o.x += bv.x; o.y += bv.y; o.z += bv.z; o.w += bv.w;
        *reinterpret_cast<float4*>(out + (m0 + tm + i) * G4H + n0 + tn) = o;
    }
}

// ---------------------------------------------------------------------------
// LSTM recurrence, mbarrier dataflow with ELECTED arrives.
// Per CTA: 2 parity mbarriers, arrive count 8 (one per producer CTA).
// Step: wait local mbar -> k-split dot (swizzled U, FFMA2) -> partials +
// __syncthreads -> combine warps compute h, remote-store slices to all 8
// peers, bar.sync(64), one elected thread: fence.acq_rel.cluster + 8 remote
// arrives. This cuts the per-mbar same-address atomic traffic 512 -> 8 per
// step (the R4 binder).
// ---------------------------------------------------------------------------
__device__ __forceinline__ float sigmoidf_(float x) {
    return __fdividef(1.f, 1.f + __expf(-x));
}

#define WS_FLOATS   (128 * HDIM)                  // 32768 floats = 128 KB
#define HBUF_OFF    WS_FLOATS                     // [2 parity][2 batch][256]
#define PART_OFF    (HBUF_OFF + 2 * 2 * HDIM)     // [2 half][4 gate][2 b][32]
#define MBAR_OFF    (PART_OFF + 512)              // 2 x u64, 8B aligned
#define REC_FLOATS  (MBAR_OFF + 8)

template <bool STORE_SEQ>
__global__ __launch_bounds__(256, 1) __cluster_dims__(CLUSTER_SZ, 1, 1)
void lstm_rec(const float* __restrict__ xw, const float* __restrict__ U,
              float* __restrict__ out_seq, float* __restrict__ out_last) {
    extern __shared__ float sm[];
    float* w_s  = sm;
    float* hbuf = sm + HBUF_OFF;
    float* part = sm + PART_OFF;

    const int tid  = threadIdx.x;       // 256
    const int half = tid >> 7;          // k-half
    const int g    = (tid >> 5) & 3;    // gate 0..3 (i,f,g,o)
    const int u    = tid & 31;          // unit within CTA slice

    uint32_t rank;
    asm("mov.u32 %0, %%cluster_ctarank;" : "=r"(rank));
    const int cid = blockIdx.x >> 3;
    const int u0  = (int)rank * 32;
    const int b0  = cid * 2;

    const uint32_t smem_b = (uint32_t)__cvta_generic_to_shared(sm);
    const uint32_t mbar_b = smem_b + MBAR_OFF * 4u;

    if (tid == 0) {
        MBARRIER_INIT(mbar_b,      CLUSTER_SZ);   // parity buffer 0
        MBARRIER_INIT(mbar_b + 8,  CLUSTER_SZ);   // parity buffer 1
    }

    // Load U slice into swizzled SMEM layout:
    //   (k, c) -> float idx ((c>>5)*64 + (k>>2))*128 + (c&31)*4 + (k&3)
    for (int idx = tid; idx < 128 * HDIM; idx += 256) {
        int k = idx >> 7;          // 0..255
        int c = idx & 127;         // gate*32 + unit
        int col = (c >> 5) * HDIM + u0 + (c & 31);
        w_s[(((c >> 5) * 64 + (k >> 2)) << 7) + ((c & 31) << 2) + (k & 3)] =
            U[(size_t)k * G4H + col];
    }
    // Zero h double-buffer + partials
    for (int idx = tid; idx < 2 * 2 * HDIM + 512; idx += 256) hbuf[idx] = 0.f;
    __syncthreads();

    // Combine-thread state (warps 0/1)
    const bool is_comb = (tid < 64);
    const int  cb  = tid >> 5;          // batch within pair
    const int  cu  = tid & 31;          // unit
    float cst = 0.f;
    float xwr0 = 0.f, xwr1 = 0.f, xwr2 = 0.f, xwr3 = 0.f;
    const size_t xbase = (size_t)(b0 + cb) * T_STEPS * G4H + u0 + cu;
    uint32_t ra_base[CLUSTER_SZ];       // mapa'd peer SMEM bases (combine only)
    if (is_comb) {
        xwr0 = xw[xbase + 0 * HDIM];
        xwr1 = xw[xbase + 1 * HDIM];
        xwr2 = xw[xbase + 2 * HDIM];
        xwr3 = xw[xbase + 3 * HDIM];
#pragma unroll
        for (int r = 0; r < CLUSTER_SZ; r++) {
            asm volatile("mapa.shared::cluster.u32 %0, %1, %2;"
                         : "=r"(ra_base[r]) : "r"(smem_b), "r"(r));
        }
    }

    // mbarriers + zeroed hbuf must be cluster-visible before any peer store.
    CLUSTER_SYNC();

    const uint32_t hbuf_b = smem_b + HBUF_OFF * 4u;
    const uint32_t w_b = smem_b + (uint32_t)g * 32768u +
                         (uint32_t)half * 16384u + (uint32_t)u * 16u;

    int ph0 = 0, ph1 = 0;

    for (int t = 0; t < T_STEPS; t++) {
        // Wait for h(t-1): it lives in buf[(t+1)&1], signaled on mbar[(t+1)&1]
        if (t > 0) {
            if (t & 1) { MBARRIER_WAIT_PARITY(mbar_b,     ph0); ph0 ^= 1; }
            else       { MBARRIER_WAIT_PARITY(mbar_b + 8, ph1); ph1 ^= 1; }
        }

        const int rd = (t + 1) & 1;
        const uint32_t h0_b = hbuf_b + (uint32_t)(rd * 2 * HDIM + half * 128) * 4u;
        const uint32_t h1_b = h0_b + HDIM * 4u;

        uint64_t a01 = 0ull, a23 = 0ull, c01 = 0ull, c23 = 0ull;
#pragma unroll
        for (int k4 = 0; k4 < 32; k4++) {
            uint64_t w01, w23, p01, p23, q01, q23;
            lds_v2u64(w01, w23, w_b + (uint32_t)k4 * 512u);  // conflict-free
            lds_v2u64(p01, p23, h0_b + (uint32_t)k4 * 16u);  // broadcast
            lds_v2u64(q01, q23, h1_b + (uint32_t)k4 * 16u);  // broadcast
            a01 = fma_x2(w01, p01, a01);
            a23 = fma_x2(w23, p23, a23);
            c01 = fma_x2(w01, q01, c01);
            c23 = fma_x2(w23, q23, c23);
        }
        float s0, s1, s2, s3, r0, r1, r2, r3;
        unpack2(a01, s0, s1); unpack2(a23, s2, s3);
        unpack2(c01, r0, r1); unpack2(c23, r2, r3);
        float pa = (s0 + s1) + (s2 + s3);
        float pb = (r0 + r1) + (r2 + r3);

        // part[half][gate][batch][unit]
        part[((half * 4 + g) * 2 + 0) * 32 + u] = pa;
        part[((half * 4 + g) * 2 + 1) * 32 + u] = pb;
        __syncthreads();

        if (is_comb) {
            float zi = xwr0 + part[(0 * 2 + cb) * 32 + cu]
                            + part[((4 + 0) * 2 + cb) * 32 + cu];
            float zf = xwr1 + part[(1 * 2 + cb) * 32 + cu]
                            + part[((4 + 1) * 2 + cb) * 32 + cu];
            float zg = xwr2 + part[(2 * 2 + cb) * 32 + cu]
                            + part[((4 + 2) * 2 + cb) * 32 + cu];
            float zo = xwr3 + part[(3 * 2 + cb) * 32 + cu]
                            + part[((4 + 3) * 2 + cb) * 32 + cu];

            float iv = sigmoidf_(zi);
            float fv = sigmoidf_(zf);
            float ov = sigmoidf_(zo);
            cst = fmaf(fv, cst, iv * zg);  // linear candidate activation
            float h = ov * cst;            // linear output activation

            if (t + 1 < T_STEPS) {
                // Push h(t) slice to all 8 peers' buf[t&1] (data only).
                const uint32_t hoff = HBUF_OFF * 4u +
                    ((uint32_t)((t & 1) * 2 * HDIM + cb * HDIM + u0 + cu) << 2);
#pragma unroll
                for (int r = 0; r < CLUSTER_SZ; r++) {
                    asm volatile("st.shared::cluster.f32 [%0], %1;"
                                 :: "r"(ra_base[r] + hoff), "f"(h) : "memory");
                }
                // All 64 combine threads' stores issued -> elected signal.
                asm volatile("bar.sync 1, 64;" ::: "memory");
                if (tid == 0) {
                    asm volatile("fence.acq_rel.cluster;" ::: "memory");
                    const uint32_t moff = MBAR_OFF * 4u + ((uint32_t)(t & 1) << 3);
#pragma unroll
                    for (int r = 0; r < CLUSTER_SZ; r++) {
                        asm volatile("mbarrier.arrive.shared::cluster.b64 _, [%0];"
                                     :: "r"(ra_base[r] + moff) : "memory");
                    }
                }
            }

            if (STORE_SEQ) {
                out_seq[((size_t)(b0 + cb) * T_STEPS + t) * HDIM + u0 + cu] = h;
            } else if (t == T_STEPS - 1) {
                out_last[(b0 + cb) * HDIM + u0 + cu] = h;
            }

            // prefetch next step's xw (after the signal is on the wire)
            if (t + 1 < T_STEPS) {
                const size_t xb = xbase + (size_t)(t + 1) * G4H;
                xwr0 = xw[xb + 0 * HDIM];
                xwr1 = xw[xb + 1 * HDIM];
                xwr2 = xw[xb + 2 * HDIM];
                xwr3 = xw[xb + 3 * HDIM];
            }
        }
        // No end-of-step barrier: next-step part/hbuf writes are ordered
        // behind the mbar wait (which requires this CTA's own prior arrive).
    }
}

// ---------------------------------------------------------------------------
// Final FC: out[32,1,128] = h1T[32,256] @ Wfc[256,128] + bfc
// ---------------------------------------------------------------------------
__global__ __launch_bounds__(128)
void fc_kernel(const float* __restrict__ h, const float* __restrict__ Wfc,
               const float* __restrict__ bfc, float* __restrict__ out) {
    const int b = blockIdx.x;
    const int j = threadIdx.x;
    const float* hb = h + b * HDIM;
    float acc = bfc[j];
#pragma unroll 16
    for (int k = 0; k < HDIM; k++)
        acc = fmaf(hb[k], Wfc[k * 128 + j], acc);
    out[b * 128 + j] = acc;
}

// ---------------------------------------------------------------------------
// Launch
// ---------------------------------------------------------------------------
#define GEMM_SMEM ((128 * 65 + 128 * 64) * 4)   // 66048
#define REC_SMEM  (REC_FLOATS * 4)              // ~137 KB

extern "C" void kernel_launch(void* const* d_in, const int* in_sizes, int n_in,
                              void* d_out, int out_size) {
    const float* x   = (const float*)d_in[0];
    const float* W0  = (const float*)d_in[1];
    const float* U0  = (const float*)d_in[2];
    const float* b0v = (const float*)d_in[3];
    const float* W1  = (const float*)d_in[4];
    const float* U1  = (const float*)d_in[5];
    const float* b1v = (const float*)d_in[6];
    const float* Wfc = (const float*)d_in[7];
    const float* bfc = (const float*)d_in[8];
    float* out = (float*)d_out;

    float *xw0, *h0seq, *xw1, *h1T;
    cudaGetSymbolAddress((void**)&xw0,   g_xw0);
    cudaGetSymbolAddress((void**)&h0seq, g_h0seq);
    cudaGetSymbolAddress((void**)&xw1,   g_xw1);
    cudaGetSymbolAddress((void**)&h1T,   g_h1T);

    cudaFuncSetAttribute(gemm_xw<128>, cudaFuncAttributeMaxDynamicSharedMemorySize, GEMM_SMEM);
    cudaFuncSetAttribute(gemm_xw<256>, cudaFuncAttributeMaxDynamicSharedMemorySize, GEMM_SMEM);
    cudaFuncSetAttribute(lstm_rec<true>,  cudaFuncAttributeMaxDynamicSharedMemorySize, REC_SMEM);
    cudaFuncSetAttribute(lstm_rec<false>, cudaFuncAttributeMaxDynamicSharedMemorySize, REC_SMEM);

    const long M = (long)NB * T_STEPS;  // 65536 rows

    gemm_xw<128><<<dim3((unsigned)(M / 64), G4H / 64), 256, GEMM_SMEM>>>(x, W0, b0v, xw0);
    lstm_rec<true><<<NB / 2 * CLUSTER_SZ, 256, REC_SMEM>>>(xw0, U0, h0seq, nullptr);
    gemm_xw<256><<<dim3((unsigned)(M / 64), G4H / 64), 256, GEMM_SMEM>>>(h0seq, W1, b1v, xw1);
    lstm_rec<false><<<NB / 2 * CLUSTER_SZ, 256, REC_SMEM>>>(xw1, U1, nullptr, h1T);
    fc_kernel<<<NB, 128>>>(h1T, Wfc, bfc, out);
}

// round 6
// speedup vs baseline: 1.2139x; 1.2139x over previous
#include <cuda_runtime.h>
#include <cstdint>
#include <cstddef>

#define T_STEPS 2048
#define NB      32
#define HDIM    256
#define G4H     1024
#define CLUSTER_SZ 8

// ---------------------------------------------------------------------------
// Scratch (device globals — no allocation allowed in kernel_launch)
// ---------------------------------------------------------------------------
__device__ float g_xw0[(size_t)NB * T_STEPS * G4H];    // 268 MB
__device__ float g_h0seq[(size_t)NB * T_STEPS * HDIM]; // 64 MB
__device__ float g_xw1[(size_t)NB * T_STEPS * G4H];    // 268 MB
__device__ float g_h1T[NB * HDIM];

// ---------------------------------------------------------------------------
// Packed fp32x2 helpers (Blackwell FFMA2 path — ptxas won't auto-fuse)
// ---------------------------------------------------------------------------
__device__ __forceinline__ uint64_t fma_x2(uint64_t a, uint64_t b, uint64_t c) {
    uint64_t d;
    asm("fma.rn.f32x2 %0, %1, %2, %3;" : "=l"(d) : "l"(a), "l"(b), "l"(c));
    return d;
}
__device__ __forceinline__ uint64_t pack2(float x, float y) {
    uint64_t d;
    asm("mov.b64 %0, {%1, %2};" : "=l"(d) : "f"(x), "f"(y));
    return d;
}
__device__ __forceinline__ void unpack2(uint64_t v, float& lo, float& hi) {
    asm("mov.b64 {%0, %1}, %2;" : "=f"(lo), "=f"(hi) : "l"(v));
}
__device__ __forceinline__ void lds_v2u64(uint64_t& a, uint64_t& b, uint32_t addr) {
    asm volatile("ld.shared.v2.u64 {%0, %1}, [%2];" : "=l"(a), "=l"(b) : "r"(addr));
}

#define MBARRIER_INIT(addr, count) \
    asm volatile("mbarrier.init.shared.b64 [%0], %1;" \
                 :: "r"((uint32_t)(addr)), "r"((uint32_t)(count)) : "memory")

// Acquire at CLUSTER scope: pairs with producers' cluster-scope arrives and
// orders our subsequent ld.shared::cluster reads of peer SMEM.
#define MBARRIER_WAIT_PARITY_CL(mbar_smem_addr, phase_parity) do { \
    uint32_t _mbar = (uint32_t)(mbar_smem_addr); \
    uint32_t _parity = (uint32_t)(phase_parity); \
    uint32_t _done; \
    asm volatile( \
        "{\n\t" \
        ".reg .pred p;\n\t" \
        "mbarrier.try_wait.parity.acquire.cluster.shared::cta.b64 p, [%1], %2;\n\t" \
        "selp.b32 %0, 1, 0, p;\n\t" \
        "}" \
        : "=r"(_done) : "r"(_mbar), "r"(_parity) : "memory"); \
    if (!_done) { \
        asm volatile( \
            "{\n\t" \
            ".reg .pred P1;\n\t" \
            "WAIT_LOOP_%=:\n\t" \
            "mbarrier.try_wait.parity.acquire.cluster.shared::cta.b64 P1, [%0], %1, 0x989680;\n\t" \
            "@P1 bra.uni WAIT_DONE_%=;\n\t" \
            "bra.uni WAIT_LOOP_%=;\n\t" \
            "WAIT_DONE_%=:\n\t" \
            "}" \
            :: "r"(_mbar), "r"(_parity) : "memory"); \
    } \
} while(0)

#define CLUSTER_SYNC() do { \
    asm volatile("barrier.cluster.arrive.aligned;" ::: "memory"); \
    asm volatile("barrier.cluster.wait.aligned;"   ::: "memory"); \
} while (0)

// ---------------------------------------------------------------------------
// GEMM: out[M x 1024] = A[M x K] @ W[K x 1024] + bias   (M = 65536)
// ---------------------------------------------------------------------------
template <int K>
__global__ __launch_bounds__(256)
void gemm_xw(const float* __restrict__ A, const float* __restrict__ W,
             const float* __restrict__ bias, float* __restrict__ out) {
    extern __shared__ float sm[];
    float* a_s = sm;               // [128][65] transposed A tile
    float* w_s = sm + 128 * 65;    // [128][64]

    const int tid = threadIdx.x;
    const long m0 = (long)blockIdx.x * 64;
    const int  n0 = blockIdx.y * 64;

    const int tn = (tid & 15) << 2;
    const int tm = (tid >> 4) << 2;

    const uint32_t ws_b = (uint32_t)__cvta_generic_to_shared(w_s);

    uint64_t acc01[4], acc23[4];
#pragma unroll
    for (int i = 0; i < 4; i++) { acc01[i] = 0ull; acc23[i] = 0ull; }

    for (int k0 = 0; k0 < K; k0 += 128) {
        for (int idx = tid; idx < 64 * 128; idx += 256) {
            int r = idx >> 7;
            int k = idx & 127;
            a_s[k * 65 + r] = A[(m0 + r) * K + k0 + k];
        }
        for (int idx = tid; idx < 128 * 16; idx += 256) {
            int k = idx >> 4, c4 = idx & 15;
            *reinterpret_cast<float4*>(w_s + k * 64 + c4 * 4) =
                *reinterpret_cast<const float4*>(W + (size_t)(k0 + k) * G4H + n0 + c4 * 4);
        }
        __syncthreads();

#pragma unroll 8
        for (int k = 0; k < 128; k++) {
            const float* ap = a_s + k * 65 + tm;
            float a0 = ap[0], a1 = ap[1], a2 = ap[2], a3 = ap[3];
            uint64_t b01, b23;
            lds_v2u64(b01, b23, ws_b + (uint32_t)(k * 64 + tn) * 4u);
            uint64_t aa;
            aa = pack2(a0, a0);
            acc01[0] = fma_x2(aa, b01, acc01[0]); acc23[0] = fma_x2(aa, b23, acc23[0]);
            aa = pack2(a1, a1);
            acc01[1] = fma_x2(aa, b01, acc01[1]); acc23[1] = fma_x2(aa, b23, acc23[1]);
            aa = pack2(a2, a2);
            acc01[2] = fma_x2(aa, b01, acc01[2]); acc23[2] = fma_x2(aa, b23, acc23[2]);
            aa = pack2(a3, a3);
            acc01[3] = fma_x2(aa, b01, acc01[3]); acc23[3] = fma_x2(aa, b23, acc23[3]);
        }
        __syncthreads();
    }

    float4 bv = *reinterpret_cast<const float4*>(bias + n0 + tn);
#pragma unroll
    for (int i = 0; i < 4; i++) {
        float4 o;
        unpack2(acc01[i], o.x, o.y);
        unpack2(acc23[i], o.z, o.w);
        o.x += bv.x; o.y += bv.y; o.z += bv.z; o.w += bv.w;
        *reinterpret_cast<float4*>(out + (m0 + tm + i) * G4H + n0 + tn) = o;
    }
}

// ---------------------------------------------------------------------------
// LSTM recurrence — PULL model.
// Producers write h(t) to a LOCAL 64-float stage (parity-buffered), drain it
// with a cheap bar.sync(64) (local STS only), and ONE elected thread sends 8
// remote mbarrier arrives (count 8, vs R4's 512 same-address atomics/step).
// Consumers acquire-wait, then PULL all 8 stages via ld.shared::cluster
// (2 KB total, no mbar involvement), assemble h in local hbuf, syncthreads,
// then run the k-split swizzled-U FFMA2 dot.
// WAR safety transitive: observing 8 arrives for h(t-1) implies every peer
// finished pulling h(t-2) (same stage parity), so stage overwrite is safe.
// ---------------------------------------------------------------------------
__device__ __forceinline__ float sigmoidf_(float x) {
    return __fdividef(1.f, 1.f + __expf(-x));
}

#define WS_FLOATS   (128 * HDIM)                  // 32768 floats = 128 KB
#define HBUF_OFF    WS_FLOATS                     // [2 batch][256] assembled h
#define STAGE_OFF   (HBUF_OFF + 512)              // [2 parity][64] own slice
#define PART_OFF    (STAGE_OFF + 128)             // [2 half][4 gate][2 b][32]
#define MBAR_OFF    (PART_OFF + 512)              // 2 x u64 (8B aligned)
#define REC_FLOATS  (MBAR_OFF + 8)

template <bool STORE_SEQ>
__global__ __launch_bounds__(256, 1) __cluster_dims__(CLUSTER_SZ, 1, 1)
void lstm_rec(const float* __restrict__ xw, const float* __restrict__ U,
              float* __restrict__ out_seq, float* __restrict__ out_last) {
    extern __shared__ float sm[];
    float* w_s  = sm;
    float* part = sm + PART_OFF;

    const int tid  = threadIdx.x;       // 256
    const int half = tid >> 7;          // k-half
    const int g    = (tid >> 5) & 3;    // gate 0..3 (i,f,g,o)
    const int u    = tid & 31;          // unit within CTA slice

    uint32_t rank;
    asm("mov.u32 %0, %%cluster_ctarank;" : "=r"(rank));
    const int cid = blockIdx.x >> 3;
    const int u0  = (int)rank * 32;
    const int b0  = cid * 2;

    const uint32_t smem_b = (uint32_t)__cvta_generic_to_shared(sm);
    const uint32_t mbar_b = smem_b + MBAR_OFF * 4u;
    const uint32_t hbuf_b = smem_b + HBUF_OFF * 4u;

    if (tid == 0) {
        MBARRIER_INIT(mbar_b,      CLUSTER_SZ);   // parity buffer 0
        MBARRIER_INIT(mbar_b + 8,  CLUSTER_SZ);   // parity buffer 1
    }

    // Load U slice into swizzled SMEM layout:
    //   (k, c) -> float idx ((c>>5)*64 + (k>>2))*128 + (c&31)*4 + (k&3)
    for (int idx = tid; idx < 128 * HDIM; idx += 256) {
        int k = idx >> 7;          // 0..255
        int c = idx & 127;         // gate*32 + unit
        int col = (c >> 5) * HDIM + u0 + (c & 31);
        w_s[(((c >> 5) * 64 + (k >> 2)) << 7) + ((c & 31) << 2) + (k & 3)] =
            U[(size_t)k * G4H + col];
    }
    // Zero assembled-h buffer + stage
    for (int idx = tid; idx < 512 + 128; idx += 256) sm[HBUF_OFF + idx] = 0.f;
    __syncthreads();

    // Pull mapping (all 256 threads): peer pr, 8 bytes each.
    const int pr  = tid >> 5;           // peer rank 0..7
    const int pq  = tid & 31;
    const int pj0 = pq * 2;             // stage float index (0..62 even)
    const int pcb = pj0 >> 5;           // batch within pair
    const int puu = pj0 & 31;           // unit within peer slice
    uint32_t ra_pull;
    asm volatile("mapa.shared::cluster.u32 %0, %1, %2;"
                 : "=r"(ra_pull) : "r"(smem_b), "r"(pr));
    const uint32_t pull_src_base = ra_pull + STAGE_OFF * 4u + (uint32_t)pj0 * 4u;
    const uint32_t pull_dst = hbuf_b + (uint32_t)(pcb * 256 + pr * 32 + puu) * 4u;

    // Combine-thread state (warps 0/1)
    const bool is_comb = (tid < 64);
    const int  cb  = tid >> 5;          // batch within pair
    const int  cu  = tid & 31;          // unit
    float cst = 0.f;
    float xwr0 = 0.f, xwr1 = 0.f, xwr2 = 0.f, xwr3 = 0.f;
    const size_t xbase = (size_t)(b0 + cb) * T_STEPS * G4H + u0 + cu;
    uint32_t ra_base[CLUSTER_SZ];       // peer SMEM bases (elect arrives)
    if (is_comb) {
        xwr0 = xw[xbase + 0 * HDIM];
        xwr1 = xw[xbase + 1 * HDIM];
        xwr2 = xw[xbase + 2 * HDIM];
        xwr3 = xw[xbase + 3 * HDIM];
#pragma unroll
        for (int r = 0; r < CLUSTER_SZ; r++) {
            asm volatile("mapa.shared::cluster.u32 %0, %1, %2;"
                         : "=r"(ra_base[r]) : "r"(smem_b), "r"(r));
        }
    }

    // mbarriers must be cluster-visible before any peer arrive.
    CLUSTER_SYNC();

    const uint32_t w_b = smem_b + (uint32_t)g * 32768u +
                         (uint32_t)half * 16384u + (uint32_t)u * 16u;
    const uint32_t h0_b = hbuf_b + (uint32_t)(half * 128) * 4u;
    const uint32_t h1_b = hbuf_b + (uint32_t)(256 + half * 128) * 4u;

    int ph0 = 0, ph1 = 0;

    for (int t = 0; t < T_STEPS; t++) {
        // Wait for h(t-1) (signaled on mbar[(t-1)&1] == mbar[(t+1)&1]),
        // then pull all 8 peers' stage slices into local hbuf.
        if (t > 0) {
            if (t & 1) { MBARRIER_WAIT_PARITY_CL(mbar_b,     ph0); ph0 ^= 1; }
            else       { MBARRIER_WAIT_PARITY_CL(mbar_b + 8, ph1); ph1 ^= 1; }
            uint64_t v;
            const uint32_t src = pull_src_base + (uint32_t)(((t + 1) & 1) * 64) * 4u;
            asm volatile("ld.shared::cluster.b64 %0, [%1];" : "=l"(v) : "r"(src));
            asm volatile("st.shared.b64 [%0], %1;" :: "r"(pull_dst), "l"(v) : "memory");
        }
        __syncthreads();   // pulled h visible to all; also fences part reuse

        uint64_t a01 = 0ull, a23 = 0ull, c01 = 0ull, c23 = 0ull;
#pragma unroll
        for (int k4 = 0; k4 < 32; k4++) {
            uint64_t w01, w23, p01, p23, q01, q23;
            lds_v2u64(w01, w23, w_b + (uint32_t)k4 * 512u);  // conflict-free
            lds_v2u64(p01, p23, h0_b + (uint32_t)k4 * 16u);  // broadcast
            lds_v2u64(q01, q23, h1_b + (uint32_t)k4 * 16u);  // broadcast
            a01 = fma_x2(w01, p01, a01);
            a23 = fma_x2(w23, p23, a23);
            c01 = fma_x2(w01, q01, c01);
            c23 = fma_x2(w23, q23, c23);
        }
        float s0, s1, s2, s3, r0, r1, r2, r3;
        unpack2(a01, s0, s1); unpack2(a23, s2, s3);
        unpack2(c01, r0, r1); unpack2(c23, r2, r3);
        float pa = (s0 + s1) + (s2 + s3);
        float pb = (r0 + r1) + (r2 + r3);

        // part[half][gate][batch][unit]
        part[((half * 4 + g) * 2 + 0) * 32 + u] = pa;
        part[((half * 4 + g) * 2 + 1) * 32 + u] = pb;
        __syncthreads();

        if (is_comb) {
            float zi = xwr0 + part[(0 * 2 + cb) * 32 + cu]
                            + part[((4 + 0) * 2 + cb) * 32 + cu];
            float zf = xwr1 + part[(1 * 2 + cb) * 32 + cu]
                            + part[((4 + 1) * 2 + cb) * 32 + cu];
            float zg = xwr2 + part[(2 * 2 + cb) * 32 + cu]
                            + part[((4 + 2) * 2 + cb) * 32 + cu];
            float zo = xwr3 + part[(3 * 2 + cb) * 32 + cu]
                            + part[((4 + 3) * 2 + cb) * 32 + cu];

            float iv = sigmoidf_(zi);
            float fv = sigmoidf_(zf);
            float ov = sigmoidf_(zo);
            cst = fmaf(fv, cst, iv * zg);  // linear candidate activation
            float h = ov * cst;            // linear output activation

            if (t + 1 < T_STEPS) {
                // Local stage write (parity t&1), drain local STS via named
                // barrier among the 64 combine threads, then 1 elected thread
                // signals all 8 peers (8 total arrives per target mbar/step).
                const uint32_t st_addr = smem_b + STAGE_OFF * 4u +
                    (uint32_t)((t & 1) * 64 + cb * 32 + cu) * 4u;
                asm volatile("st.shared.f32 [%0], %1;"
                             :: "r"(st_addr), "f"(h) : "memory");
                asm volatile("bar.sync 1, 64;" ::: "memory");
                if (tid == 0) {
                    const uint32_t moff = MBAR_OFF * 4u + ((uint32_t)(t & 1) << 3);
#pragma unroll
                    for (int r = 0; r < CLUSTER_SZ; r++) {
                        asm volatile("mbarrier.arrive.shared::cluster.b64 _, [%0];"
                                     :: "r"(ra_base[r] + moff) : "memory");
                    }
                }
            }

            if (STORE_SEQ) {
                out_seq[((size_t)(b0 + cb) * T_STEPS + t) * HDIM + u0 + cu] = h;
            } else if (t == T_STEPS - 1) {
                out_last[(b0 + cb) * HDIM + u0 + cu] = h;
            }

            // prefetch next step's xw (after the signal is on the wire)
            if (t + 1 < T_STEPS) {
                const size_t xb = xbase + (size_t)(t + 1) * G4H;
                xwr0 = xw[xb + 0 * HDIM];
                xwr1 = xw[xb + 1 * HDIM];
                xwr2 = xw[xb + 2 * HDIM];
                xwr3 = xw[xb + 3 * HDIM];
            }
        }
        // No end-of-step barrier: next-step hbuf/part writes are ordered
        // behind the mbar wait (which requires this CTA's own prior arrive).
    }
}

// ---------------------------------------------------------------------------
// Final FC: out[32,1,128] = h1T[32,256] @ Wfc[256,128] + bfc
// ---------------------------------------------------------------------------
__global__ __launch_bounds__(128)
void fc_kernel(const float* __restrict__ h, const float* __restrict__ Wfc,
               const float* __restrict__ bfc, float* __restrict__ out) {
    const int b = blockIdx.x;
    const int j = threadIdx.x;
    const float* hb = h + b * HDIM;
    float acc = bfc[j];
#pragma unroll 16
    for (int k = 0; k < HDIM; k++)
        acc = fmaf(hb[k], Wfc[k * 128 + j], acc);
    out[b * 128 + j] = acc;
}

// ---------------------------------------------------------------------------
// Launch
// ---------------------------------------------------------------------------
#define GEMM_SMEM ((128 * 65 + 128 * 64) * 4)   // 66048
#define REC_SMEM  (REC_FLOATS * 4)              // ~133 KB

extern "C" void kernel_launch(void* const* d_in, const int* in_sizes, int n_in,
                              void* d_out, int out_size) {
    const float* x   = (const float*)d_in[0];
    const float* W0  = (const float*)d_in[1];
    const float* U0  = (const float*)d_in[2];
    const float* b0v = (const float*)d_in[3];
    const float* W1  = (const float*)d_in[4];
    const float* U1  = (const float*)d_in[5];
    const float* b1v = (const float*)d_in[6];
    const float* Wfc = (const float*)d_in[7];
    const float* bfc = (const float*)d_in[8];
    float* out = (float*)d_out;

    float *xw0, *h0seq, *xw1, *h1T;
    cudaGetSymbolAddress((void**)&xw0,   g_xw0);
    cudaGetSymbolAddress((void**)&h0seq, g_h0seq);
    cudaGetSymbolAddress((void**)&xw1,   g_xw1);
    cudaGetSymbolAddress((void**)&h1T,   g_h1T);

    cudaFuncSetAttribute(gemm_xw<128>, cudaFuncAttributeMaxDynamicSharedMemorySize, GEMM_SMEM);
    cudaFuncSetAttribute(gemm_xw<256>, cudaFuncAttributeMaxDynamicSharedMemorySize, GEMM_SMEM);
    cudaFuncSetAttribute(lstm_rec<true>,  cudaFuncAttributeMaxDynamicSharedMemorySize, REC_SMEM);
    cudaFuncSetAttribute(lstm_rec<false>, cudaFuncAttributeMaxDynamicSharedMemorySize, REC_SMEM);

    const long M = (long)NB * T_STEPS;  // 65536 rows

    gemm_xw<128><<<dim3((unsigned)(M / 64), G4H / 64), 256, GEMM_SMEM>>>(x, W0, b0v, xw0);
    lstm_rec<true><<<NB / 2 * CLUSTER_SZ, 256, REC_SMEM>>>(xw0, U0, h0seq, nullptr);
    gemm_xw<256><<<dim3((unsigned)(M / 64), G4H / 64), 256, GEMM_SMEM>>>(h0seq, W1, b1v, xw1);
    lstm_rec<false><<<NB / 2 * CLUSTER_SZ, 256, REC_SMEM>>>(xw1, U1, nullptr, h1T);
    fc_kernel<<<NB, 128>>>(h1T, Wfc, bfc, out);
}